// round 3
// baseline (speedup 1.0000x reference)
#include <cuda_runtime.h>
#include <math.h>

// ---------------- problem constants ----------------
#define Bsz    64
#define Dm     768
#define Hn     12
#define DHd    64
#define Lnum   12
#define FFd    3072
#define NPRn   8
#define STOK   205            // 197 + 8 prompts
#define NPATCH 196
#define MTOK   (Bsz*STOK)     // 13120  (divisible by 64)
#define MPATCH (Bsz*NPATCH)   // 12544  (divisible by 64)

// ---------------- static device scratch (no allocations allowed) ----------------
__device__ float g_x [MTOK*Dm];     // activations [B,S,D]
__device__ float g_h [MTOK*Dm];     // layernorm output / conv feat
__device__ float g_q [MTOK*Dm];
__device__ float g_k [MTOK*Dm];
__device__ float g_v [MTOK*Dm];
__device__ float g_a [MTOK*Dm];     // attention output
__device__ float g_col[MPATCH*Dm];  // im2col buffer
__device__ float g_ff[MTOK*FFd];    // MLP hidden

// ---------------- helpers ----------------
__device__ __forceinline__ float qgelu(float x) {
    // x * sigmoid(1.702 x)
    return x / (1.f + expf(-1.702f * x));
}

// ---------------- im2col for the patch conv ----------------
// out[m][k], m = b*196 + p (p = py*14+px), k = c*256 + i*16 + j
__global__ __launch_bounds__(256) void im2col_kernel(const float* __restrict__ img,
                                                     float* __restrict__ out) {
    int idx = blockIdx.x * blockDim.x + threadIdx.x;
    if (idx >= MPATCH * Dm) return;
    int k = idx % Dm;
    int m = idx / Dm;
    int b = m / NPATCH;
    int p = m % NPATCH;
    int py = p / 14, px = p % 14;
    int c = k >> 8;           // 256 per channel
    int i = (k >> 4) & 15;
    int j = k & 15;
    out[idx] = img[(((size_t)b * 3 + c) * 224 + (py * 16 + i)) * 224 + (px * 16 + j)];
}

// ---------------- assemble x = [CLS+pos ; feat+pos ; prompts(layer0)] ----------------
__global__ __launch_bounds__(256) void assemble_kernel(const float* __restrict__ feat,
                                                       const float* __restrict__ cls,
                                                       const float* __restrict__ pos,
                                                       const float* __restrict__ gp,
                                                       float* __restrict__ x) {
    int idx = blockIdx.x * blockDim.x + threadIdx.x;
    if (idx >= MTOK * Dm) return;
    int d = idx % Dm;
    int s = (idx / Dm) % STOK;
    int b = idx / (Dm * STOK);
    float v;
    if (s == 0)            v = cls[d] + pos[d];
    else if (s < 197)      v = feat[((size_t)(b * NPATCH + s - 1)) * Dm + d] + pos[(size_t)s * Dm + d];
    else                   v = gp[(((size_t)b * Lnum + 0) * NPRn + (s - 197)) * Dm + d];
    x[idx] = v;
}

// ---------------- replace last NPR tokens with layer-l prompts ----------------
__global__ __launch_bounds__(256) void replace_kernel(float* __restrict__ x,
                                                      const float* __restrict__ gp,
                                                      int layer) {
    int idx = blockIdx.x * blockDim.x + threadIdx.x;
    if (idx >= Bsz * NPRn * Dm) return;
    int d = idx % Dm;
    int r = (idx / Dm) % NPRn;
    int b = idx / (Dm * NPRn);
    x[((size_t)(b * STOK + 197 + r)) * Dm + d] =
        gp[(((size_t)b * Lnum + layer) * NPRn + r) * Dm + d];
}

// ---------------- LayerNorm (one block per row, D=768, 256 threads) ----------------
__global__ __launch_bounds__(256) void ln_kernel(const float* __restrict__ x,
                                                 const float* __restrict__ g,
                                                 const float* __restrict__ b,
                                                 float* __restrict__ out,
                                                 int in_stride, int out_stride) {
    const float* xr = x + (size_t)blockIdx.x * in_stride;
    float* orow = out + (size_t)blockIdx.x * out_stride;
    int t = threadIdx.x;
    float v0 = xr[t], v1 = xr[t + 256], v2 = xr[t + 512];
    float s = v0 + v1 + v2;
    float q = v0 * v0 + v1 * v1 + v2 * v2;
#pragma unroll
    for (int off = 16; off; off >>= 1) {
        s += __shfl_xor_sync(0xffffffffu, s, off);
        q += __shfl_xor_sync(0xffffffffu, q, off);
    }
    __shared__ float ws[8], wq[8], stat[2];
    int w = t >> 5, lane = t & 31;
    if (lane == 0) { ws[w] = s; wq[w] = q; }
    __syncthreads();
    if (t < 32) {
        float s2 = (t < 8) ? ws[t] : 0.f;
        float q2 = (t < 8) ? wq[t] : 0.f;
#pragma unroll
        for (int off = 4; off; off >>= 1) {
            s2 += __shfl_xor_sync(0xffffffffu, s2, off);
            q2 += __shfl_xor_sync(0xffffffffu, q2, off);
        }
        if (t == 0) {
            float mean = s2 * (1.f / 768.f);
            float var  = q2 * (1.f / 768.f) - mean * mean;
            stat[0] = mean;
            stat[1] = rsqrtf(var + 1e-5f);
        }
    }
    __syncthreads();
    float mean = stat[0], inv = stat[1];
    orow[t]       = (v0 - mean) * inv * g[t]       + b[t];
    orow[t + 256] = (v1 - mean) * inv * g[t + 256] + b[t + 256];
    orow[t + 512] = (v2 - mean) * inv * g[t + 512] + b[t + 512];
}

// ---------------- SGEMM: C[M,N] = A[M,K] @ W[N,K]^T (+bias)(+epilogue) ----------------
// MODE 0: +bias; MODE 1: (+bias)*alpha; MODE 2: +bias+res; MODE 3: quick_gelu(+bias)
// Requires M%64==0, N%64==0, K%16==0 (all shapes here satisfy this).
template <int MODE>
__global__ __launch_bounds__(256)
void gemm_kernel(const float* __restrict__ A, const float* __restrict__ W,
                 const float* __restrict__ bias, const float* __restrict__ res,
                 float* __restrict__ C, int M, int N, int K, float alpha) {
    __shared__ float As[16][64];
    __shared__ float Bs[16][64];
    int tx = threadIdx.x, ty = threadIdx.y;
    int tid = ty * 16 + tx;
    int m0 = blockIdx.y * 64, n0 = blockIdx.x * 64;
    int lr = tid >> 2;
    int lc = (tid & 3) << 2;
    const float* Aptr = A + (size_t)(m0 + lr) * K + lc;
    const float* Wptr = W + (size_t)(n0 + lr) * K + lc;
    float acc[4][4];
#pragma unroll
    for (int i = 0; i < 4; i++)
#pragma unroll
        for (int j = 0; j < 4; j++) acc[i][j] = 0.f;

    for (int k0 = 0; k0 < K; k0 += 16) {
        float4 a4 = *(const float4*)(Aptr + k0);
        float4 w4 = *(const float4*)(Wptr + k0);
        As[lc + 0][lr] = a4.x; As[lc + 1][lr] = a4.y;
        As[lc + 2][lr] = a4.z; As[lc + 3][lr] = a4.w;
        Bs[lc + 0][lr] = w4.x; Bs[lc + 1][lr] = w4.y;
        Bs[lc + 2][lr] = w4.z; Bs[lc + 3][lr] = w4.w;
        __syncthreads();
#pragma unroll
        for (int kk = 0; kk < 16; kk++) {
            float4 av = *(const float4*)&As[kk][ty << 2];
            float4 bv = *(const float4*)&Bs[kk][tx << 2];
            float ar[4] = {av.x, av.y, av.z, av.w};
            float br[4] = {bv.x, bv.y, bv.z, bv.w};
#pragma unroll
            for (int i = 0; i < 4; i++)
#pragma unroll
                for (int j = 0; j < 4; j++) acc[i][j] += ar[i] * br[j];
        }
        __syncthreads();
    }

    float4 b4 = make_float4(0.f, 0.f, 0.f, 0.f);
    if (bias) b4 = *(const float4*)(bias + n0 + (tx << 2));
#pragma unroll
    for (int i = 0; i < 4; i++) {
        int m = m0 + (ty << 2) + i;
        float4 r;
        r.x = acc[i][0] + b4.x;
        r.y = acc[i][1] + b4.y;
        r.z = acc[i][2] + b4.z;
        r.w = acc[i][3] + b4.w;
        if (MODE == 1) { r.x *= alpha; r.y *= alpha; r.z *= alpha; r.w *= alpha; }
        if (MODE == 2) {
            float4 rr = *(const float4*)(res + (size_t)m * N + n0 + (tx << 2));
            r.x += rr.x; r.y += rr.y; r.z += rr.z; r.w += rr.w;
        }
        if (MODE == 3) {
            r.x = qgelu(r.x); r.y = qgelu(r.y); r.z = qgelu(r.z); r.w = qgelu(r.w);
        }
        *(float4*)(C + (size_t)m * N + n0 + (tx << 2)) = r;
    }
}

// ---------------- fused attention: one block per (b,h), K/V staged in smem ----------------
// smem: sK[205][65], sV[205][65], sQ[8 warps][64]
__global__ __launch_bounds__(256)
void attn_kernel(const float* __restrict__ q, const float* __restrict__ k,
                 const float* __restrict__ v, float* __restrict__ o) {
    extern __shared__ float sm[];
    float* sK = sm;
    float* sV = sm + STOK * 65;
    float* sQ = sm + 2 * STOK * 65;
    int bh = blockIdx.x;
    int b = bh / Hn, hh = bh % Hn;
    int tid = threadIdx.x;
    size_t base = (size_t)b * STOK * Dm + (size_t)hh * DHd;

    for (int idx = tid; idx < STOK * DHd; idx += 256) {
        int j = idx >> 6, d = idx & 63;
        size_t g = base + (size_t)j * Dm + d;
        sK[j * 65 + d] = k[g];
        sV[j * 65 + d] = v[g];
    }
    __syncthreads();

    int warp = tid >> 5, lane = tid & 31;
    for (int i = warp; i < STOK; i += 8) {
        const float* qr = q + base + (size_t)i * Dm;
        sQ[warp * 64 + lane]      = qr[lane];
        sQ[warp * 64 + lane + 32] = qr[lane + 32];
        __syncwarp();

        float e[7];
        float mx = -1e30f;
#pragma unroll
        for (int jj = 0; jj < 7; jj++) {
            int j = lane + jj * 32;
            float s = -1e30f;
            if (j < STOK) {
                s = 0.f;
#pragma unroll
                for (int d = 0; d < DHd; d++)
                    s += sQ[warp * 64 + d] * sK[j * 65 + d];
            }
            e[jj] = s;
            mx = fmaxf(mx, s);
        }
#pragma unroll
        for (int off = 16; off; off >>= 1)
            mx = fmaxf(mx, __shfl_xor_sync(0xffffffffu, mx, off));

        float sum = 0.f;
#pragma unroll
        for (int jj = 0; jj < 7; jj++) {
            int j = lane + jj * 32;
            float ev = (j < STOK) ? expf(e[jj] - mx) : 0.f;
            e[jj] = ev;
            sum += ev;
        }
#pragma unroll
        for (int off = 16; off; off >>= 1)
            sum += __shfl_xor_sync(0xffffffffu, sum, off);
        float inv = 1.f / sum;

        float o0 = 0.f, o1 = 0.f;
#pragma unroll
        for (int jj = 0; jj < 7; jj++) {
            int jbase = jj * 32;
            int lim = STOK - jbase; if (lim > 32) lim = 32;
            for (int src = 0; src < lim; src++) {
                float w = __shfl_sync(0xffffffffu, e[jj], src);
                int j = jbase + src;
                o0 += w * sV[j * 65 + lane];
                o1 += w * sV[j * 65 + lane + 32];
            }
        }
        o0 *= inv; o1 *= inv;
        size_t og = base + (size_t)i * Dm;
        o[og + lane]      = o0;
        o[og + lane + 32] = o1;
        __syncwarp();
    }
}

// ---------------- host orchestration ----------------
extern "C" void kernel_launch(void* const* d_in, const int* in_sizes, int n_in,
                              void* d_out, int out_size) {
    const float* image   = (const float*)d_in[0];
    const float* gprompt = (const float*)d_in[1];
    const float* patch_w = (const float*)d_in[2];
    const float* cls_emb = (const float*)d_in[3];
    const float* pos_emb = (const float*)d_in[4];
    const float* pre_g   = (const float*)d_in[5];
    const float* pre_b   = (const float*)d_in[6];
    const float* ln1_g   = (const float*)d_in[7];
    const float* ln1_b   = (const float*)d_in[8];
    const float* qw      = (const float*)d_in[9];
    const float* qb      = (const float*)d_in[10];
    const float* kw      = (const float*)d_in[11];
    const float* kb      = (const float*)d_in[12];
    const float* vw      = (const float*)d_in[13];
    const float* vb      = (const float*)d_in[14];
    const float* ow      = (const float*)d_in[15];
    const float* ob      = (const float*)d_in[16];
    const float* ln2_g   = (const float*)d_in[17];
    const float* ln2_b   = (const float*)d_in[18];
    const float* fc1_w   = (const float*)d_in[19];
    const float* fc1_b   = (const float*)d_in[20];
    const float* fc2_w   = (const float*)d_in[21];
    const float* fc2_b   = (const float*)d_in[22];
    const float* post_g  = (const float*)d_in[23];
    const float* post_b  = (const float*)d_in[24];
    float* out = (float*)d_out;

    float *x, *h, *q, *k, *v, *a, *col, *ff;
    cudaGetSymbolAddress((void**)&x,  g_x);
    cudaGetSymbolAddress((void**)&h,  g_h);
    cudaGetSymbolAddress((void**)&q,  g_q);
    cudaGetSymbolAddress((void**)&k,  g_k);
    cudaGetSymbolAddress((void**)&v,  g_v);
    cudaGetSymbolAddress((void**)&a,  g_a);
    cudaGetSymbolAddress((void**)&col, g_col);
    cudaGetSymbolAddress((void**)&ff, g_ff);

    const int attn_smem = (2 * STOK * 65 + 8 * 64) * (int)sizeof(float); // 108,648 B
    cudaFuncSetAttribute(attn_kernel, cudaFuncAttributeMaxDynamicSharedMemorySize, attn_smem);

    dim3 blk(16, 16);
    dim3 g768(Dm / 64, MTOK / 64);    // [12, 205]
    dim3 gff(FFd / 64, MTOK / 64);    // [48, 205]

    // --- embeddings: im2col + conv GEMM + assemble + pre-LN ---
    {
        int tot = MPATCH * Dm;
        im2col_kernel<<<(tot + 255) / 256, 256>>>(image, col);
        dim3 gc(Dm / 64, MPATCH / 64);
        gemm_kernel<0><<<gc, blk>>>(col, patch_w, nullptr, nullptr, h, MPATCH, Dm, Dm, 1.f);
        tot = MTOK * Dm;
        assemble_kernel<<<(tot + 255) / 256, 256>>>(h, cls_emb, pos_emb, gprompt, x);
        ln_kernel<<<MTOK, 256>>>(x, pre_g, pre_b, x, Dm, Dm);
    }

    for (int l = 0; l < Lnum; l++) {
        if (l > 0) {
            int tot = Bsz * NPRn * Dm;
            replace_kernel<<<(tot + 255) / 256, 256>>>(x, gprompt, l);
        }
        // attention
        ln_kernel<<<MTOK, 256>>>(x, ln1_g + (size_t)l * Dm, ln1_b + (size_t)l * Dm, h, Dm, Dm);
        gemm_kernel<1><<<g768, blk>>>(h, qw + (size_t)l * Dm * Dm, qb + (size_t)l * Dm,
                                      nullptr, q, MTOK, Dm, Dm, 0.125f);
        gemm_kernel<0><<<g768, blk>>>(h, kw + (size_t)l * Dm * Dm, kb + (size_t)l * Dm,
                                      nullptr, k, MTOK, Dm, Dm, 1.f);
        gemm_kernel<0><<<g768, blk>>>(h, vw + (size_t)l * Dm * Dm, vb + (size_t)l * Dm,
                                      nullptr, v, MTOK, Dm, Dm, 1.f);
        attn_kernel<<<Bsz * Hn, 256, attn_smem>>>(q, k, v, a);
        gemm_kernel<2><<<g768, blk>>>(a, ow + (size_t)l * Dm * Dm, ob + (size_t)l * Dm,
                                      x, x, MTOK, Dm, Dm, 1.f);
        // MLP
        ln_kernel<<<MTOK, 256>>>(x, ln2_g + (size_t)l * Dm, ln2_b + (size_t)l * Dm, h, Dm, Dm);
        gemm_kernel<3><<<gff, blk>>>(h, fc1_w + (size_t)l * FFd * Dm, fc1_b + (size_t)l * FFd,
                                     nullptr, ff, MTOK, FFd, Dm, 1.f);
        gemm_kernel<2><<<g768, blk>>>(ff, fc2_w + (size_t)l * Dm * FFd, fc2_b + (size_t)l * Dm,
                                      x, x, MTOK, Dm, FFd, 1.f);
    }

    // final LN of CLS token only: row b -> x[b*205 + 0], out stride D
    ln_kernel<<<Bsz, 256>>>(x, post_g, post_b, out, STOK * Dm, Dm);
}

// round 4
// speedup vs baseline: 2.2035x; 2.2035x over previous
#include <cuda_runtime.h>
#include <cuda_bf16.h>
#include <math.h>

// ---------------- problem constants ----------------
#define Bsz    64
#define Dm     768
#define Hn     12
#define DHd    64
#define Lnum   12
#define FFd    3072
#define NPRn   8
#define STOK   205
#define NPATCH 196
#define MTOK   (Bsz*STOK)     // 13120
#define MPATCH (Bsz*NPATCH)   // 12544 = 98*128
#define MPAD   13184          // 103*128 >= MTOK
#define K768E  2304           // 3*768 expanded K
#define KFFE   9216           // 3*3072 expanded K

// ---------------- static device scratch ----------------
__device__ float g_x[MPAD*Dm];
__device__ float g_q[MPAD*Dm];
__device__ float g_k[MPAD*Dm];
__device__ float g_v[MPAD*Dm];
__device__ __nv_bfloat16 g_ae1[(size_t)MPAD*K768E];     // expanded activations (K=768 GEMMs)
__device__ __nv_bfloat16 g_ae2[(size_t)MPAD*KFFE];      // expanded MLP hidden
__device__ __nv_bfloat16 g_wq[(size_t)Lnum*Dm*K768E];
__device__ __nv_bfloat16 g_wk[(size_t)Lnum*Dm*K768E];
__device__ __nv_bfloat16 g_wv[(size_t)Lnum*Dm*K768E];
__device__ __nv_bfloat16 g_wo[(size_t)Lnum*Dm*K768E];
__device__ __nv_bfloat16 g_w1[(size_t)Lnum*FFd*K768E];
__device__ __nv_bfloat16 g_w2[(size_t)Lnum*Dm*KFFE];
__device__ __nv_bfloat16 g_wp[(size_t)Dm*K768E];

// ---------------- helpers ----------------
__device__ __forceinline__ float qgelu(float x) {
    return x / (1.f + expf(-1.702f * x));
}
__device__ __forceinline__ void split_bf(float v, __nv_bfloat16& hi, __nv_bfloat16& lo) {
    hi = __float2bfloat16(v);
    lo = __float2bfloat16(v - __bfloat162float(hi));
}
__device__ __forceinline__ void cp16(void* s, const void* g) {
    unsigned sa = (unsigned)__cvta_generic_to_shared(s);
    asm volatile("cp.async.ca.shared.global [%0], [%1], 16;\n" :: "r"(sa), "l"(g));
}
__device__ __forceinline__ void ldm4(unsigned* r, const __nv_bfloat16* p) {
    unsigned s = (unsigned)__cvta_generic_to_shared(p);
    asm volatile("ldmatrix.sync.aligned.m8n8.x4.shared.b16 {%0,%1,%2,%3}, [%4];"
                 : "=r"(r[0]), "=r"(r[1]), "=r"(r[2]), "=r"(r[3]) : "r"(s));
}
__device__ __forceinline__ void mma16816(float* d, const unsigned* a, unsigned b0, unsigned b1) {
    asm volatile("mma.sync.aligned.m16n8k16.row.col.f32.bf16.bf16.f32 "
                 "{%0,%1,%2,%3}, {%4,%5,%6,%7}, {%8,%9}, {%0,%1,%2,%3};"
                 : "+f"(d[0]), "+f"(d[1]), "+f"(d[2]), "+f"(d[3])
                 : "r"(a[0]), "r"(a[1]), "r"(a[2]), "r"(a[3]), "r"(b0), "r"(b1));
}

// ---------------- weight conversion: fp32 [R,K] -> bf16 [R,3K] as (hi, lo, hi) ----------------
__global__ __launch_bounds__(256) void wconv_kernel(const float* __restrict__ src,
                                                    __nv_bfloat16* __restrict__ dst,
                                                    int R, int K) {
    long long idx = (long long)blockIdx.x * 256 + threadIdx.x;
    if (idx >= (long long)R * K) return;
    int k = (int)(idx % K);
    long long r = idx / K;
    float w = src[idx];
    __nv_bfloat16 hi, lo;
    split_bf(w, hi, lo);
    size_t b = (size_t)r * 3 * K;
    dst[b + k]         = hi;
    dst[b + K + k]     = lo;
    dst[b + 2 * K + k] = hi;
}

// ---------------- im2col + expand: image -> ae1 [MPATCH, 2304] as (hi, hi, lo) ----------------
__global__ __launch_bounds__(256) void im2col_exp_kernel(const float* __restrict__ img,
                                                         __nv_bfloat16* __restrict__ out) {
    int idx = blockIdx.x * 256 + threadIdx.x;
    if (idx >= MPATCH * Dm) return;
    int k = idx % Dm;
    int m = idx / Dm;
    int b = m / NPATCH, p = m % NPATCH;
    int py = p / 14, px = p % 14;
    int c = k >> 8, i = (k >> 4) & 15, j = k & 15;
    float v = img[(((size_t)b * 3 + c) * 224 + (py * 16 + i)) * 224 + (px * 16 + j)];
    __nv_bfloat16 hi, lo;
    split_bf(v, hi, lo);
    size_t base = (size_t)m * K768E;
    out[base + k]          = hi;
    out[base + Dm + k]     = hi;
    out[base + 2 * Dm + k] = lo;
}

// ---------------- assemble x = [CLS+pos ; feat+pos ; prompts(layer0)] ----------------
__global__ __launch_bounds__(256) void assemble_kernel(const float* __restrict__ feat,
                                                       const float* __restrict__ cls,
                                                       const float* __restrict__ pos,
                                                       const float* __restrict__ gp,
                                                       float* __restrict__ x) {
    int idx = blockIdx.x * blockDim.x + threadIdx.x;
    if (idx >= MTOK * Dm) return;
    int d = idx % Dm;
    int s = (idx / Dm) % STOK;
    int b = idx / (Dm * STOK);
    float v;
    if (s == 0)       v = cls[d] + pos[d];
    else if (s < 197) v = feat[((size_t)(b * NPATCH + s - 1)) * Dm + d] + pos[(size_t)s * Dm + d];
    else              v = gp[(((size_t)b * Lnum + 0) * NPRn + (s - 197)) * Dm + d];
    x[idx] = v;
}

__global__ __launch_bounds__(256) void replace_kernel(float* __restrict__ x,
                                                      const float* __restrict__ gp,
                                                      int layer) {
    int idx = blockIdx.x * blockDim.x + threadIdx.x;
    if (idx >= Bsz * NPRn * Dm) return;
    int d = idx % Dm;
    int r = (idx / Dm) % NPRn;
    int b = idx / (Dm * NPRn);
    x[((size_t)(b * STOK + 197 + r)) * Dm + d] =
        gp[(((size_t)b * Lnum + layer) * NPRn + r) * Dm + d];
}

// ---------------- LayerNorm: EXPOUT=0 fp32 out, EXPOUT=1 expanded-bf16 out (stride 2304) ------
template <int EXPOUT>
__global__ __launch_bounds__(256) void ln_kernel(const float* __restrict__ x,
                                                 const float* __restrict__ g,
                                                 const float* __restrict__ bb,
                                                 void* __restrict__ outp,
                                                 int in_stride, int out_stride) {
    const float* xr = x + (size_t)blockIdx.x * in_stride;
    int t = threadIdx.x;
    float v0 = xr[t], v1 = xr[t + 256], v2 = xr[t + 512];
    float s = v0 + v1 + v2;
    float q = v0 * v0 + v1 * v1 + v2 * v2;
#pragma unroll
    for (int off = 16; off; off >>= 1) {
        s += __shfl_xor_sync(0xffffffffu, s, off);
        q += __shfl_xor_sync(0xffffffffu, q, off);
    }
    __shared__ float ws[8], wq[8], stat[2];
    int w = t >> 5, lane = t & 31;
    if (lane == 0) { ws[w] = s; wq[w] = q; }
    __syncthreads();
    if (t < 32) {
        float s2 = (t < 8) ? ws[t] : 0.f;
        float q2 = (t < 8) ? wq[t] : 0.f;
#pragma unroll
        for (int off = 4; off; off >>= 1) {
            s2 += __shfl_xor_sync(0xffffffffu, s2, off);
            q2 += __shfl_xor_sync(0xffffffffu, q2, off);
        }
        if (t == 0) {
            float mean = s2 * (1.f / 768.f);
            float var  = q2 * (1.f / 768.f) - mean * mean;
            stat[0] = mean;
            stat[1] = rsqrtf(var + 1e-5f);
        }
    }
    __syncthreads();
    float mean = stat[0], inv = stat[1];
    float y0 = (v0 - mean) * inv * g[t]       + bb[t];
    float y1 = (v1 - mean) * inv * g[t + 256] + bb[t + 256];
    float y2 = (v2 - mean) * inv * g[t + 512] + bb[t + 512];
    if (EXPOUT) {
        __nv_bfloat16* o = (__nv_bfloat16*)outp + (size_t)blockIdx.x * K768E;
        __nv_bfloat16 h0, l0, h1, l1, h2, l2;
        split_bf(y0, h0, l0); split_bf(y1, h1, l1); split_bf(y2, h2, l2);
        o[t]        = h0; o[768 + t]        = h0; o[1536 + t]        = l0;
        o[t + 256]  = h1; o[768 + t + 256]  = h1; o[1536 + t + 256]  = l1;
        o[t + 512]  = h2; o[768 + t + 512]  = h2; o[1536 + t + 512]  = l2;
    } else {
        float* o = (float*)outp + (size_t)blockIdx.x * out_stride;
        o[t] = y0; o[t + 256] = y1; o[t + 512] = y2;
    }
}

// ---------------- bf16 tensor-core GEMM: C[M,N] = A[M,Kp] @ W[N,Kp]^T ----------------
// MODE 0: +bias fp32 out; 1: (+bias)*alpha; 2: +bias+res; 3: quick_gelu(+bias) -> expanded bf16
#define BMt 128
#define BNt 128
#define BKt 32
#define SKS 40   // padded K stride in bf16 (80B rows -> conflict-free ldmatrix)

template <int MODE>
__global__ __launch_bounds__(256, 2)
void bgemm_kernel(const __nv_bfloat16* __restrict__ A, const __nv_bfloat16* __restrict__ W,
                  const float* __restrict__ bias, const float* __restrict__ res,
                  void* __restrict__ Cout, int Kp, int N, int Mreal, float alpha) {
    __shared__ __nv_bfloat16 sA[2][BMt * SKS];
    __shared__ __nv_bfloat16 sB[2][BMt * SKS];
    int tid = threadIdx.x, lane = tid & 31, warp = tid >> 5;
    int m0 = blockIdx.y * BMt, n0 = blockIdx.x * BNt;
    int wm = (warp >> 2) * 64, wn = (warp & 3) * 32;
    float acc[4][4][4];
#pragma unroll
    for (int i = 0; i < 4; i++)
#pragma unroll
        for (int j = 0; j < 4; j++)
#pragma unroll
            for (int e = 0; e < 4; e++) acc[i][j][e] = 0.f;

    auto load_stage = [&](int st, int k0) {
#pragma unroll
        for (int i = 0; i < 2; i++) {
            int c = tid + i * 256;
            int row = c >> 2, ko = (c & 3) << 3;
            cp16(&sA[st][row * SKS + ko], A + (size_t)(m0 + row) * Kp + k0 + ko);
            cp16(&sB[st][row * SKS + ko], W + (size_t)(n0 + row) * Kp + k0 + ko);
        }
        asm volatile("cp.async.commit_group;\n");
    };

    load_stage(0, 0);
    int nk = Kp / BKt;
    for (int t = 0; t < nk; t++) {
        if (t + 1 < nk) {
            load_stage((t + 1) & 1, (t + 1) * BKt);
            asm volatile("cp.async.wait_group 1;\n");
        } else {
            asm volatile("cp.async.wait_group 0;\n");
        }
        __syncthreads();
        const __nv_bfloat16* as = sA[t & 1];
        const __nv_bfloat16* bs = sB[t & 1];
#pragma unroll
        for (int kk = 0; kk < 2; kk++) {
            int kof = kk * 16 + ((lane >> 4) << 3);
            int rrow = lane & 15;
            unsigned ar[4][4];
#pragma unroll
            for (int mi = 0; mi < 4; mi++)
                ldm4(ar[mi], &as[(wm + mi * 16 + rrow) * SKS + kof]);
            unsigned br[2][4];
#pragma unroll
            for (int p = 0; p < 2; p++)
                ldm4(br[p], &bs[(wn + p * 16 + rrow) * SKS + kof]);
#pragma unroll
            for (int mi = 0; mi < 4; mi++)
#pragma unroll
                for (int nj = 0; nj < 4; nj++)
                    mma16816(acc[mi][nj], ar[mi], br[nj >> 1][nj & 1], br[nj >> 1][(nj & 1) + 2]);
        }
        __syncthreads();
    }

    // epilogue
    int group = lane >> 2, tig = lane & 3;
#pragma unroll
    for (int mi = 0; mi < 4; mi++) {
#pragma unroll
        for (int nj = 0; nj < 4; nj++) {
            int col = n0 + wn + nj * 8 + tig * 2;
            float bx = 0.f, by = 0.f;
            if (bias) { bx = bias[col]; by = bias[col + 1]; }
#pragma unroll
            for (int h = 0; h < 2; h++) {
                int row = m0 + wm + mi * 16 + group + h * 8;
                if (row >= Mreal) continue;
                float c0 = acc[mi][nj][h * 2 + 0] + bx;
                float c1 = acc[mi][nj][h * 2 + 1] + by;
                if (MODE == 1) { c0 *= alpha; c1 *= alpha; }
                if (MODE == 2) {
                    float2 rr = *(const float2*)(res + (size_t)row * N + col);
                    c0 += rr.x; c1 += rr.y;
                }
                if (MODE == 3) {
                    c0 = qgelu(c0); c1 = qgelu(c1);
                    __nv_bfloat16 h0, l0, h1, l1;
                    split_bf(c0, h0, l0); split_bf(c1, h1, l1);
                    __nv_bfloat16* Cb = (__nv_bfloat16*)Cout;
                    size_t base = (size_t)row * (3 * N) + col;
                    __nv_bfloat162 hp; hp.x = h0; hp.y = h1;
                    __nv_bfloat162 lp; lp.x = l0; lp.y = l1;
                    *(__nv_bfloat162*)(Cb + base)         = hp;
                    *(__nv_bfloat162*)(Cb + base + N)     = hp;
                    *(__nv_bfloat162*)(Cb + base + 2 * N) = lp;
                } else {
                    *(float2*)((float*)Cout + (size_t)row * N + col) = make_float2(c0, c1);
                }
            }
        }
    }
}

// ---------------- fused attention: one block per (b,h); expanded-bf16 output ----------------
__global__ __launch_bounds__(256)
void attn_kernel(const float* __restrict__ q, const float* __restrict__ k,
                 const float* __restrict__ v, __nv_bfloat16* __restrict__ o) {
    extern __shared__ float sm[];
    float* sK = sm;
    float* sV = sm + STOK * 65;
    float* sQ = sm + 2 * STOK * 65;
    int bh = blockIdx.x;
    int b = bh / Hn, hh = bh % Hn;
    int tid = threadIdx.x;
    size_t base = (size_t)b * STOK * Dm + (size_t)hh * DHd;

    for (int idx = tid; idx < STOK * DHd; idx += 256) {
        int j = idx >> 6, d = idx & 63;
        size_t gg = base + (size_t)j * Dm + d;
        sK[j * 65 + d] = k[gg];
        sV[j * 65 + d] = v[gg];
    }
    __syncthreads();

    int warp = tid >> 5, lane = tid & 31;
    for (int i = warp; i < STOK; i += 8) {
        const float* qr = q + base + (size_t)i * Dm;
        sQ[warp * 64 + lane]      = qr[lane];
        sQ[warp * 64 + lane + 32] = qr[lane + 32];
        __syncwarp();

        float e[7];
        float mx = -1e30f;
#pragma unroll
        for (int jj = 0; jj < 7; jj++) {
            int j = lane + jj * 32;
            float s = -1e30f;
            if (j < STOK) {
                s = 0.f;
#pragma unroll
                for (int d = 0; d < DHd; d++)
                    s += sQ[warp * 64 + d] * sK[j * 65 + d];
            }
            e[jj] = s;
            mx = fmaxf(mx, s);
        }
#pragma unroll
        for (int off = 16; off; off >>= 1)
            mx = fmaxf(mx, __shfl_xor_sync(0xffffffffu, mx, off));

        float sum = 0.f;
#pragma unroll
        for (int jj = 0; jj < 7; jj++) {
            int j = lane + jj * 32;
            float ev = (j < STOK) ? expf(e[jj] - mx) : 0.f;
            e[jj] = ev;
            sum += ev;
        }
#pragma unroll
        for (int off = 16; off; off >>= 1)
            sum += __shfl_xor_sync(0xffffffffu, sum, off);
        float inv = 1.f / sum;

        float o0 = 0.f, o1 = 0.f;
#pragma unroll
        for (int jj = 0; jj < 7; jj++) {
            int jbase = jj * 32;
            int lim = STOK - jbase; if (lim > 32) lim = 32;
            for (int src = 0; src < lim; src++) {
                float wv2 = __shfl_sync(0xffffffffu, e[jj], src);
                int j = jbase + src;
                o0 += wv2 * sV[j * 65 + lane];
                o1 += wv2 * sV[j * 65 + lane + 32];
            }
        }
        o0 *= inv; o1 *= inv;
        // write expanded (hi, hi, lo) at row (b*STOK+i), cols hh*64 + lane/(+32)
        size_t orow = ((size_t)(b * STOK + i)) * K768E + hh * DHd;
        __nv_bfloat16 h0, l0, h1, l1;
        split_bf(o0, h0, l0); split_bf(o1, h1, l1);
        o[orow + lane]              = h0;
        o[orow + 768 + lane]        = h0;
        o[orow + 1536 + lane]       = l0;
        o[orow + lane + 32]         = h1;
        o[orow + 768 + lane + 32]   = h1;
        o[orow + 1536 + lane + 32]  = l1;
        __syncwarp();
    }
}

// ---------------- host orchestration ----------------
extern "C" void kernel_launch(void* const* d_in, const int* in_sizes, int n_in,
                              void* d_out, int out_size) {
    const float* image   = (const float*)d_in[0];
    const float* gprompt = (const float*)d_in[1];
    const float* patch_w = (const float*)d_in[2];
    const float* cls_emb = (const float*)d_in[3];
    const float* pos_emb = (const float*)d_in[4];
    const float* pre_g   = (const float*)d_in[5];
    const float* pre_b   = (const float*)d_in[6];
    const float* ln1_g   = (const float*)d_in[7];
    const float* ln1_b   = (const float*)d_in[8];
    const float* qw      = (const float*)d_in[9];
    const float* qb      = (const float*)d_in[10];
    const float* kw      = (const float*)d_in[11];
    const float* kb      = (const float*)d_in[12];
    const float* vw      = (const float*)d_in[13];
    const float* vb      = (const float*)d_in[14];
    const float* ow      = (const float*)d_in[15];
    const float* ob      = (const float*)d_in[16];
    const float* ln2_g   = (const float*)d_in[17];
    const float* ln2_b   = (const float*)d_in[18];
    const float* fc1_w   = (const float*)d_in[19];
    const float* fc1_b   = (const float*)d_in[20];
    const float* fc2_w   = (const float*)d_in[21];
    const float* fc2_b   = (const float*)d_in[22];
    const float* post_g  = (const float*)d_in[23];
    const float* post_b  = (const float*)d_in[24];
    float* out = (float*)d_out;

    float *x, *q, *k, *v;
    __nv_bfloat16 *ae1, *ae2, *wqd, *wkd, *wvd, *wod, *w1d, *w2d, *wpd;
    cudaGetSymbolAddress((void**)&x,   g_x);
    cudaGetSymbolAddress((void**)&q,   g_q);
    cudaGetSymbolAddress((void**)&k,   g_k);
    cudaGetSymbolAddress((void**)&v,   g_v);
    cudaGetSymbolAddress((void**)&ae1, g_ae1);
    cudaGetSymbolAddress((void**)&ae2, g_ae2);
    cudaGetSymbolAddress((void**)&wqd, g_wq);
    cudaGetSymbolAddress((void**)&wkd, g_wk);
    cudaGetSymbolAddress((void**)&wvd, g_wv);
    cudaGetSymbolAddress((void**)&wod, g_wo);
    cudaGetSymbolAddress((void**)&w1d, g_w1);
    cudaGetSymbolAddress((void**)&w2d, g_w2);
    cudaGetSymbolAddress((void**)&wpd, g_wp);

    const int attn_smem = (2 * STOK * 65 + 8 * 64) * (int)sizeof(float);
    cudaFuncSetAttribute(attn_kernel, cudaFuncAttributeMaxDynamicSharedMemorySize, attn_smem);

    // --- weight conversions (per launch; graph-capturable, no allocs) ---
    {
        long long n;
        n = (long long)Lnum * Dm * Dm;
        wconv_kernel<<<(unsigned)((n + 255) / 256), 256>>>(qw, wqd, Lnum * Dm, Dm);
        wconv_kernel<<<(unsigned)((n + 255) / 256), 256>>>(kw, wkd, Lnum * Dm, Dm);
        wconv_kernel<<<(unsigned)((n + 255) / 256), 256>>>(vw, wvd, Lnum * Dm, Dm);
        wconv_kernel<<<(unsigned)((n + 255) / 256), 256>>>(ow, wod, Lnum * Dm, Dm);
        n = (long long)Lnum * FFd * Dm;
        wconv_kernel<<<(unsigned)((n + 255) / 256), 256>>>(fc1_w, w1d, Lnum * FFd, Dm);
        n = (long long)Lnum * Dm * FFd;
        wconv_kernel<<<(unsigned)((n + 255) / 256), 256>>>(fc2_w, w2d, Lnum * Dm, FFd);
        n = (long long)Dm * Dm;
        wconv_kernel<<<(unsigned)((n + 255) / 256), 256>>>(patch_w, wpd, Dm, Dm);
    }

    // --- embeddings ---
    im2col_exp_kernel<<<(MPATCH * Dm + 255) / 256, 256>>>(image, ae1);
    bgemm_kernel<0><<<dim3(Dm / BNt, MPATCH / BMt), 256>>>(
        ae1, wpd, nullptr, nullptr, q, K768E, Dm, MPATCH, 1.f);
    assemble_kernel<<<(MTOK * Dm + 255) / 256, 256>>>(q, cls_emb, pos_emb, gprompt, x);
    ln_kernel<0><<<MTOK, 256>>>(x, pre_g, pre_b, x, Dm, Dm);

    dim3 g768(Dm / BNt, MPAD / BMt);   // (6, 103)
    dim3 gff(FFd / BNt, MPAD / BMt);   // (24, 103)

    for (int l = 0; l < Lnum; l++) {
        if (l > 0) {
            int tot = Bsz * NPRn * Dm;
            replace_kernel<<<(tot + 255) / 256, 256>>>(x, gprompt, l);
        }
        // attention
        ln_kernel<1><<<MTOK, 256>>>(x, ln1_g + (size_t)l * Dm, ln1_b + (size_t)l * Dm, ae1, Dm, 0);
        bgemm_kernel<1><<<g768, 256>>>(ae1, wqd + (size_t)l * Dm * K768E, qb + (size_t)l * Dm,
                                       nullptr, q, K768E, Dm, MTOK, 0.125f);
        bgemm_kernel<0><<<g768, 256>>>(ae1, wkd + (size_t)l * Dm * K768E, kb + (size_t)l * Dm,
                                       nullptr, k, K768E, Dm, MTOK, 1.f);
        bgemm_kernel<0><<<g768, 256>>>(ae1, wvd + (size_t)l * Dm * K768E, vb + (size_t)l * Dm,
                                       nullptr, v, K768E, Dm, MTOK, 1.f);
        attn_kernel<<<Bsz * Hn, 256, attn_smem>>>(q, k, v, ae1);
        bgemm_kernel<2><<<g768, 256>>>(ae1, wod + (size_t)l * Dm * K768E, ob + (size_t)l * Dm,
                                       x, x, K768E, Dm, MTOK, 1.f);
        // MLP
        ln_kernel<1><<<MTOK, 256>>>(x, ln2_g + (size_t)l * Dm, ln2_b + (size_t)l * Dm, ae1, Dm, 0);
        bgemm_kernel<3><<<gff, 256>>>(ae1, w1d + (size_t)l * FFd * K768E, fc1_b + (size_t)l * FFd,
                                      nullptr, ae2, K768E, FFd, MTOK, 1.f);
        bgemm_kernel<2><<<g768, 256>>>(ae2, w2d + (size_t)l * Dm * KFFE, fc2_b + (size_t)l * Dm,
                                       x, x, KFFE, Dm, MTOK, 1.f);
    }

    ln_kernel<0><<<Bsz, 256>>>(x, post_g, post_b, out, STOK * Dm, Dm);
}

// round 5
// speedup vs baseline: 2.2986x; 1.0431x over previous
#include <cuda_runtime.h>
#include <cuda_bf16.h>
#include <math.h>

// ---------------- problem constants ----------------
#define Bsz    64
#define Dm     768
#define Hn     12
#define DHd    64
#define Lnum   12
#define FFd    3072
#define NPRn   8
#define STOK   205
#define NPATCH 196
#define MTOK   (Bsz*STOK)     // 13120
#define MPATCH (Bsz*NPATCH)   // 12544 = 98*128
#define MPAD   13184          // 103*128 >= MTOK
#define K768E  2304           // 3*768 expanded K
#define KFFE   9216           // 3*3072 expanded K
#define NQKV   2304           // fused q|k|v output width

// ---------------- static device scratch ----------------
__device__ float g_x[MPAD*Dm];
__device__ float g_qkv[(size_t)MPAD*NQKV];              // packed q|k|v fp32
__device__ __nv_bfloat16 g_ae1[(size_t)MPAD*K768E];     // expanded activations (K=768 GEMMs)
__device__ __nv_bfloat16 g_ae2[(size_t)MPAD*KFFE];      // expanded MLP hidden
__device__ __nv_bfloat16 g_wqkv[(size_t)Lnum*NQKV*K768E];
__device__ float         g_bqkv[(size_t)Lnum*NQKV];
__device__ __nv_bfloat16 g_wo[(size_t)Lnum*Dm*K768E];
__device__ __nv_bfloat16 g_w1[(size_t)Lnum*FFd*K768E];
__device__ __nv_bfloat16 g_w2[(size_t)Lnum*Dm*KFFE];
__device__ __nv_bfloat16 g_wp[(size_t)Dm*K768E];

// ---------------- helpers ----------------
__device__ __forceinline__ float qgelu(float x) {
    return x / (1.f + expf(-1.702f * x));
}
__device__ __forceinline__ void split_bf(float v, __nv_bfloat16& hi, __nv_bfloat16& lo) {
    hi = __float2bfloat16(v);
    lo = __float2bfloat16(v - __bfloat162float(hi));
}
__device__ __forceinline__ void cp16(void* s, const void* g) {
    unsigned sa = (unsigned)__cvta_generic_to_shared(s);
    asm volatile("cp.async.ca.shared.global [%0], [%1], 16;\n" :: "r"(sa), "l"(g));
}
__device__ __forceinline__ void ldm4(unsigned* r, const __nv_bfloat16* p) {
    unsigned s = (unsigned)__cvta_generic_to_shared(p);
    asm volatile("ldmatrix.sync.aligned.m8n8.x4.shared.b16 {%0,%1,%2,%3}, [%4];"
                 : "=r"(r[0]), "=r"(r[1]), "=r"(r[2]), "=r"(r[3]) : "r"(s));
}
__device__ __forceinline__ void mma16816(float* d, const unsigned* a, unsigned b0, unsigned b1) {
    asm volatile("mma.sync.aligned.m16n8k16.row.col.f32.bf16.bf16.f32 "
                 "{%0,%1,%2,%3}, {%4,%5,%6,%7}, {%8,%9}, {%0,%1,%2,%3};"
                 : "+f"(d[0]), "+f"(d[1]), "+f"(d[2]), "+f"(d[3])
                 : "r"(a[0]), "r"(a[1]), "r"(a[2]), "r"(a[3]), "r"(b0), "r"(b1));
}

// ---------------- weight conversion: fp32 [R,K] -> bf16 [R,3K] as (hi, lo, hi) ----------------
__global__ __launch_bounds__(256) void wconv_kernel(const float* __restrict__ src,
                                                    __nv_bfloat16* __restrict__ dst,
                                                    int R, int K) {
    long long idx = (long long)blockIdx.x * 256 + threadIdx.x;
    if (idx >= (long long)R * K) return;
    int k = (int)(idx % K);
    long long r = idx / K;
    float w = src[idx];
    __nv_bfloat16 hi, lo;
    split_bf(w, hi, lo);
    size_t b = (size_t)r * 3 * K;
    dst[b + k]         = hi;
    dst[b + K + k]     = lo;
    dst[b + 2 * K + k] = hi;
}

// ---------------- fused QKV weight conversion (scale folded into q rows) ----------------
__global__ __launch_bounds__(256) void wconv_qkv_kernel(const float* __restrict__ qw,
                                                        const float* __restrict__ kw,
                                                        const float* __restrict__ vw,
                                                        __nv_bfloat16* __restrict__ dst) {
    long long idx = (long long)blockIdx.x * 256 + threadIdx.x;
    if (idx >= (long long)Lnum * NQKV * Dm) return;
    int k = (int)(idx % Dm);
    long long rowall = idx / Dm;          // l*2304 + rr
    int rr = (int)(rowall % NQKV);
    int l  = (int)(rowall / NQKV);
    float w;
    if (rr < 768)        w = qw[((size_t)l * Dm + rr) * Dm + k] * 0.125f;
    else if (rr < 1536)  w = kw[((size_t)l * Dm + (rr - 768)) * Dm + k];
    else                 w = vw[((size_t)l * Dm + (rr - 1536)) * Dm + k];
    __nv_bfloat16 hi, lo;
    split_bf(w, hi, lo);
    size_t b = (size_t)rowall * K768E;
    dst[b + k]            = hi;
    dst[b + Dm + k]       = lo;
    dst[b + 2 * Dm + k]   = hi;
}

__global__ __launch_bounds__(256) void bconv_qkv_kernel(const float* __restrict__ qb,
                                                        const float* __restrict__ kb,
                                                        const float* __restrict__ vb,
                                                        float* __restrict__ out) {
    int idx = blockIdx.x * 256 + threadIdx.x;
    if (idx >= Lnum * NQKV) return;
    int rr = idx % NQKV, l = idx / NQKV;
    float v;
    if (rr < 768)       v = qb[l * Dm + rr] * 0.125f;
    else if (rr < 1536) v = kb[l * Dm + (rr - 768)];
    else                v = vb[l * Dm + (rr - 1536)];
    out[idx] = v;
}

// ---------------- im2col + expand: image -> ae1 [MPATCH, 2304] as (hi, hi, lo) ----------------
__global__ __launch_bounds__(256) void im2col_exp_kernel(const float* __restrict__ img,
                                                         __nv_bfloat16* __restrict__ out) {
    int idx = blockIdx.x * 256 + threadIdx.x;
    if (idx >= MPATCH * Dm) return;
    int k = idx % Dm;
    int m = idx / Dm;
    int b = m / NPATCH, p = m % NPATCH;
    int py = p / 14, px = p % 14;
    int c = k >> 8, i = (k >> 4) & 15, j = k & 15;
    float v = img[(((size_t)b * 3 + c) * 224 + (py * 16 + i)) * 224 + (px * 16 + j)];
    __nv_bfloat16 hi, lo;
    split_bf(v, hi, lo);
    size_t base = (size_t)m * K768E;
    out[base + k]          = hi;
    out[base + Dm + k]     = hi;
    out[base + 2 * Dm + k] = lo;
}

// ---------------- assemble x = [CLS+pos ; feat+pos ; prompts(layer0)] ----------------
__global__ __launch_bounds__(256) void assemble_kernel(const float* __restrict__ feat,
                                                       const float* __restrict__ cls,
                                                       const float* __restrict__ pos,
                                                       const float* __restrict__ gp,
                                                       float* __restrict__ x) {
    int idx = blockIdx.x * blockDim.x + threadIdx.x;
    if (idx >= MTOK * Dm) return;
    int d = idx % Dm;
    int s = (idx / Dm) % STOK;
    int b = idx / (Dm * STOK);
    float v;
    if (s == 0)       v = cls[d] + pos[d];
    else if (s < 197) v = feat[((size_t)(b * NPATCH + s - 1)) * Dm + d] + pos[(size_t)s * Dm + d];
    else              v = gp[(((size_t)b * Lnum + 0) * NPRn + (s - 197)) * Dm + d];
    x[idx] = v;
}

__global__ __launch_bounds__(256) void replace_kernel(float* __restrict__ x,
                                                      const float* __restrict__ gp,
                                                      int layer) {
    int idx = blockIdx.x * blockDim.x + threadIdx.x;
    if (idx >= Bsz * NPRn * Dm) return;
    int d = idx % Dm;
    int r = (idx / Dm) % NPRn;
    int b = idx / (Dm * NPRn);
    x[((size_t)(b * STOK + 197 + r)) * Dm + d] =
        gp[(((size_t)b * Lnum + layer) * NPRn + r) * Dm + d];
}

// ---------------- LayerNorm: EXPOUT=0 fp32 out, EXPOUT=1 expanded-bf16 out (stride 2304) ------
template <int EXPOUT>
__global__ __launch_bounds__(256) void ln_kernel(const float* __restrict__ x,
                                                 const float* __restrict__ g,
                                                 const float* __restrict__ bb,
                                                 void* __restrict__ outp,
                                                 int in_stride, int out_stride) {
    const float* xr = x + (size_t)blockIdx.x * in_stride;
    int t = threadIdx.x;
    float v0 = xr[t], v1 = xr[t + 256], v2 = xr[t + 512];
    float s = v0 + v1 + v2;
    float q = v0 * v0 + v1 * v1 + v2 * v2;
#pragma unroll
    for (int off = 16; off; off >>= 1) {
        s += __shfl_xor_sync(0xffffffffu, s, off);
        q += __shfl_xor_sync(0xffffffffu, q, off);
    }
    __shared__ float ws[8], wq[8], stat[2];
    int w = t >> 5, lane = t & 31;
    if (lane == 0) { ws[w] = s; wq[w] = q; }
    __syncthreads();
    if (t < 32) {
        float s2 = (t < 8) ? ws[t] : 0.f;
        float q2 = (t < 8) ? wq[t] : 0.f;
#pragma unroll
        for (int off = 4; off; off >>= 1) {
            s2 += __shfl_xor_sync(0xffffffffu, s2, off);
            q2 += __shfl_xor_sync(0xffffffffu, q2, off);
        }
        if (t == 0) {
            float mean = s2 * (1.f / 768.f);
            float var  = q2 * (1.f / 768.f) - mean * mean;
            stat[0] = mean;
            stat[1] = rsqrtf(var + 1e-5f);
        }
    }
    __syncthreads();
    float mean = stat[0], inv = stat[1];
    float y0 = (v0 - mean) * inv * g[t]       + bb[t];
    float y1 = (v1 - mean) * inv * g[t + 256] + bb[t + 256];
    float y2 = (v2 - mean) * inv * g[t + 512] + bb[t + 512];
    if (EXPOUT) {
        __nv_bfloat16* o = (__nv_bfloat16*)outp + (size_t)blockIdx.x * K768E;
        __nv_bfloat16 h0, l0, h1, l1, h2, l2;
        split_bf(y0, h0, l0); split_bf(y1, h1, l1); split_bf(y2, h2, l2);
        o[t]        = h0; o[768 + t]        = h0; o[1536 + t]        = l0;
        o[t + 256]  = h1; o[768 + t + 256]  = h1; o[1536 + t + 256]  = l1;
        o[t + 512]  = h2; o[768 + t + 512]  = h2; o[1536 + t + 512]  = l2;
    } else {
        float* o = (float*)outp + (size_t)blockIdx.x * out_stride;
        o[t] = y0; o[t + 256] = y1; o[t + 512] = y2;
    }
}

// ---------------- bf16 tensor-core GEMM: C[M,N] = A[M,Kp] @ W[N,Kp]^T ----------------
// MODE 0: +bias fp32 out; 2: +bias+res fp32 out; 3: quick_gelu(+bias) -> expanded bf16
#define BMt 128
#define BNt 128
#define BKt 32
#define SKS 40   // padded K stride in bf16 (80B rows -> conflict-free ldmatrix)
#define STAGE_ELEMS (BMt*SKS)
#define GEMM_SMEM (6*STAGE_ELEMS*2)   // 3 stages x (A+B), bytes

template <int MODE>
__global__ __launch_bounds__(256, 2)
void bgemm_kernel(const __nv_bfloat16* __restrict__ A, const __nv_bfloat16* __restrict__ W,
                  const float* __restrict__ bias, const float* __restrict__ res,
                  void* __restrict__ Cout, int Kp, int N, int Mreal, int resStride) {
    extern __shared__ __nv_bfloat16 smem[];
    __nv_bfloat16* sAb = smem;                      // 3 * STAGE_ELEMS
    __nv_bfloat16* sBb = smem + 3 * STAGE_ELEMS;    // 3 * STAGE_ELEMS
    int tid = threadIdx.x, lane = tid & 31, warp = tid >> 5;
    int m0 = blockIdx.y * BMt, n0 = blockIdx.x * BNt;
    int wm = (warp >> 2) * 64, wn = (warp & 3) * 32;
    float acc[4][4][4];
#pragma unroll
    for (int i = 0; i < 4; i++)
#pragma unroll
        for (int j = 0; j < 4; j++)
#pragma unroll
            for (int e = 0; e < 4; e++) acc[i][j][e] = 0.f;

    int lrow = tid >> 2, lko = (tid & 3) << 3;
    int lrow2 = (tid + 256) >> 2, lko2 = ((tid + 256) & 3) << 3;

    auto load_stage = [&](int st, int k0) {
        __nv_bfloat16* a = sAb + st * STAGE_ELEMS;
        __nv_bfloat16* b = sBb + st * STAGE_ELEMS;
        cp16(a + lrow * SKS + lko,  A + (size_t)(m0 + lrow) * Kp + k0 + lko);
        cp16(b + lrow * SKS + lko,  W + (size_t)(n0 + lrow) * Kp + k0 + lko);
        cp16(a + lrow2 * SKS + lko2, A + (size_t)(m0 + lrow2) * Kp + k0 + lko2);
        cp16(b + lrow2 * SKS + lko2, W + (size_t)(n0 + lrow2) * Kp + k0 + lko2);
        asm volatile("cp.async.commit_group;\n");
    };

    int nk = Kp / BKt;   // >= 72 for all shapes here
    load_stage(0, 0);
    load_stage(1, BKt);

    int cs = 0, ls = 2;
    for (int t = 0; t < nk; t++) {
        if (t + 1 < nk) asm volatile("cp.async.wait_group 1;\n");
        else            asm volatile("cp.async.wait_group 0;\n");
        __syncthreads();
        if (t + 2 < nk) load_stage(ls, (t + 2) * BKt);
        ls = (ls == 2) ? 0 : ls + 1;

        const __nv_bfloat16* as = sAb + cs * STAGE_ELEMS;
        const __nv_bfloat16* bs = sBb + cs * STAGE_ELEMS;
        cs = (cs == 2) ? 0 : cs + 1;
#pragma unroll
        for (int kk = 0; kk < 2; kk++) {
            int kof = kk * 16 + ((lane >> 4) << 3);
            int rrow = lane & 15;
            unsigned ar[4][4];
#pragma unroll
            for (int mi = 0; mi < 4; mi++)
                ldm4(ar[mi], &as[(wm + mi * 16 + rrow) * SKS + kof]);
            unsigned br[2][4];
#pragma unroll
            for (int p = 0; p < 2; p++)
                ldm4(br[p], &bs[(wn + p * 16 + rrow) * SKS + kof]);
#pragma unroll
            for (int mi = 0; mi < 4; mi++)
#pragma unroll
                for (int nj = 0; nj < 4; nj++)
                    mma16816(acc[mi][nj], ar[mi], br[nj >> 1][nj & 1], br[nj >> 1][(nj & 1) + 2]);
        }
        // no trailing sync: next iter's top sync protects the stage being overwritten
        __syncthreads();
    }

    // epilogue
    int group = lane >> 2, tig = lane & 3;
#pragma unroll
    for (int mi = 0; mi < 4; mi++) {
#pragma unroll
        for (int nj = 0; nj < 4; nj++) {
            int col = n0 + wn + nj * 8 + tig * 2;
            float bx = 0.f, by = 0.f;
            if (bias) { bx = bias[col]; by = bias[col + 1]; }
#pragma unroll
            for (int h = 0; h < 2; h++) {
                int row = m0 + wm + mi * 16 + group + h * 8;
                if (row >= Mreal) continue;
                float c0 = acc[mi][nj][h * 2 + 0] + bx;
                float c1 = acc[mi][nj][h * 2 + 1] + by;
                if (MODE == 2) {
                    float2 rr = *(const float2*)(res + (size_t)row * resStride + col);
                    c0 += rr.x; c1 += rr.y;
                }
                if (MODE == 3) {
                    c0 = qgelu(c0); c1 = qgelu(c1);
                    __nv_bfloat16 h0, l0, h1, l1;
                    split_bf(c0, h0, l0); split_bf(c1, h1, l1);
                    __nv_bfloat16* Cb = (__nv_bfloat16*)Cout;
                    size_t base = (size_t)row * (3 * N) + col;
                    __nv_bfloat162 hp; hp.x = h0; hp.y = h1;
                    __nv_bfloat162 lp; lp.x = l0; lp.y = l1;
                    *(__nv_bfloat162*)(Cb + base)         = hp;
                    *(__nv_bfloat162*)(Cb + base + N)     = hp;
                    *(__nv_bfloat162*)(Cb + base + 2 * N) = lp;
                } else {
                    *(float2*)((float*)Cout + (size_t)row * N + col) = make_float2(c0, c1);
                }
            }
        }
    }
}

// ---------------- fused attention: one block per (b,h); packed qkv input ----------------
// smem layout (floats): sK[205*65] | sV[205*65] | sQ[8*64] | sP[8*208]
#define ATTN_SMEM_FLOATS (2*STOK*65 + 8*64 + 8*208)
__global__ __launch_bounds__(256)
void attn_kernel(const float* __restrict__ qkv, __nv_bfloat16* __restrict__ o) {
    extern __shared__ float sm[];
    float* sK = sm;
    float* sV = sm + STOK * 65;
    float* sQ = sm + 2 * STOK * 65;
    float* sP = sQ + 8 * 64;
    int bh = blockIdx.x;
    int b = bh / Hn, hh = bh % Hn;
    int tid = threadIdx.x;
    size_t base = (size_t)b * STOK * NQKV + (size_t)hh * DHd;

    for (int idx = tid; idx < STOK * DHd; idx += 256) {
        int j = idx >> 6, d = idx & 63;
        size_t gg = base + (size_t)j * NQKV + d;
        sK[j * 65 + d] = qkv[gg + 768];
        sV[j * 65 + d] = qkv[gg + 1536];
    }
    __syncthreads();

    int warp = tid >> 5, lane = tid & 31;
    for (int i = warp; i < STOK; i += 8) {
        const float* qr = qkv + base + (size_t)i * NQKV;
        sQ[warp * 64 + lane]      = qr[lane];
        sQ[warp * 64 + lane + 32] = qr[lane + 32];
        __syncwarp();

        float e[7];
        float mx = -1e30f;
#pragma unroll
        for (int jj = 0; jj < 7; jj++) {
            int j = lane + jj * 32;
            float s = -1e30f;
            if (j < STOK) {
                s = 0.f;
#pragma unroll
                for (int d = 0; d < DHd; d++)
                    s += sQ[warp * 64 + d] * sK[j * 65 + d];
            }
            e[jj] = s;
            mx = fmaxf(mx, s);
        }
#pragma unroll
        for (int off = 16; off; off >>= 1)
            mx = fmaxf(mx, __shfl_xor_sync(0xffffffffu, mx, off));

        float sum = 0.f;
#pragma unroll
        for (int jj = 0; jj < 7; jj++) {
            int j = lane + jj * 32;
            float ev = (j < STOK) ? expf(e[jj] - mx) : 0.f;
            e[jj] = ev;
            sum += ev;
        }
#pragma unroll
        for (int off = 16; off; off >>= 1)
            sum += __shfl_xor_sync(0xffffffffu, sum, off);
        float inv = 1.f / sum;

        // probabilities -> smem, then broadcast-read PV accumulation (no SHFL chain)
#pragma unroll
        for (int jj = 0; jj < 7; jj++) {
            int j = lane + jj * 32;
            if (j < STOK) sP[warp * 208 + j] = e[jj] * inv;
        }
        __syncwarp();

        float o0 = 0.f, o1 = 0.f;
        const float* pw = sP + warp * 208;
#pragma unroll 5
        for (int j = 0; j < STOK; j++) {
            float w = pw[j];
            o0 += w * sV[j * 65 + lane];
            o1 += w * sV[j * 65 + lane + 32];
        }
        // write expanded (hi, hi, lo) at row (b*STOK+i), cols hh*64 + lane/(+32)
        size_t orow = ((size_t)(b * STOK + i)) * K768E + hh * DHd;
        __nv_bfloat16 h0, l0, h1, l1;
        split_bf(o0, h0, l0); split_bf(o1, h1, l1);
        o[orow + lane]              = h0;
        o[orow + 768 + lane]        = h0;
        o[orow + 1536 + lane]       = l0;
        o[orow + lane + 32]         = h1;
        o[orow + 768 + lane + 32]   = h1;
        o[orow + 1536 + lane + 32]  = l1;
        __syncwarp();
    }
}

// ---------------- host orchestration ----------------
extern "C" void kernel_launch(void* const* d_in, const int* in_sizes, int n_in,
                              void* d_out, int out_size) {
    const float* image   = (const float*)d_in[0];
    const float* gprompt = (const float*)d_in[1];
    const float* patch_w = (const float*)d_in[2];
    const float* cls_emb = (const float*)d_in[3];
    const float* pos_emb = (const float*)d_in[4];
    const float* pre_g   = (const float*)d_in[5];
    const float* pre_b   = (const float*)d_in[6];
    const float* ln1_g   = (const float*)d_in[7];
    const float* ln1_b   = (const float*)d_in[8];
    const float* qw      = (const float*)d_in[9];
    const float* qb      = (const float*)d_in[10];
    const float* kw      = (const float*)d_in[11];
    const float* kb      = (const float*)d_in[12];
    const float* vw      = (const float*)d_in[13];
    const float* vb      = (const float*)d_in[14];
    const float* ow      = (const float*)d_in[15];
    const float* ob      = (const float*)d_in[16];
    const float* ln2_g   = (const float*)d_in[17];
    const float* ln2_b   = (const float*)d_in[18];
    const float* fc1_w   = (const float*)d_in[19];
    const float* fc1_b   = (const float*)d_in[20];
    const float* fc2_w   = (const float*)d_in[21];
    const float* fc2_b   = (const float*)d_in[22];
    const float* post_g  = (const float*)d_in[23];
    const float* post_b  = (const float*)d_in[24];
    float* out = (float*)d_out;

    float *x, *qkv, *bqkv;
    __nv_bfloat16 *ae1, *ae2, *wqkvd, *wod, *w1d, *w2d, *wpd;
    cudaGetSymbolAddress((void**)&x,    g_x);
    cudaGetSymbolAddress((void**)&qkv,  g_qkv);
    cudaGetSymbolAddress((void**)&bqkv, g_bqkv);
    cudaGetSymbolAddress((void**)&ae1,  g_ae1);
    cudaGetSymbolAddress((void**)&ae2,  g_ae2);
    cudaGetSymbolAddress((void**)&wqkvd, g_wqkv);
    cudaGetSymbolAddress((void**)&wod,  g_wo);
    cudaGetSymbolAddress((void**)&w1d,  g_w1);
    cudaGetSymbolAddress((void**)&w2d,  g_w2);
    cudaGetSymbolAddress((void**)&wpd,  g_wp);

    const int attn_smem = ATTN_SMEM_FLOATS * (int)sizeof(float);
    cudaFuncSetAttribute(attn_kernel, cudaFuncAttributeMaxDynamicSharedMemorySize, attn_smem);
    cudaFuncSetAttribute(bgemm_kernel<0>, cudaFuncAttributeMaxDynamicSharedMemorySize, GEMM_SMEM);
    cudaFuncSetAttribute(bgemm_kernel<2>, cudaFuncAttributeMaxDynamicSharedMemorySize, GEMM_SMEM);
    cudaFuncSetAttribute(bgemm_kernel<3>, cudaFuncAttributeMaxDynamicSharedMemorySize, GEMM_SMEM);

    // --- launch ordering chosen so launch #5 (1-based) is a representative bgemm for ncu ---
    {
        long long n;
        n = (long long)Dm * Dm;                                           // 1: patch wconv
        wconv_kernel<<<(unsigned)((n + 255) / 256), 256>>>(patch_w, wpd, Dm, Dm);
        im2col_exp_kernel<<<(MPATCH * Dm + 255) / 256, 256>>>(image, ae1); // 2
        n = (long long)Lnum * NQKV * Dm;                                   // 3: fused qkv wconv
        wconv_qkv_kernel<<<(unsigned)((n + 255) / 256), 256>>>(qw, kw, vw, wqkvd);
        bconv_qkv_kernel<<<(Lnum * NQKV + 255) / 256, 256>>>(qb, kb, vb, bqkv); // 4
        // 5: conv GEMM (profiled by ncu -s)
        bgemm_kernel<0><<<dim3(Dm / BNt, MPATCH / BMt), 256, GEMM_SMEM>>>(
            ae1, wpd, nullptr, nullptr, qkv, K768E, Dm, MPATCH, 0);
        assemble_kernel<<<(MTOK * Dm + 255) / 256, 256>>>(qkv, cls_emb, pos_emb, gprompt, x); // 6
        ln_kernel<0><<<MTOK, 256>>>(x, pre_g, pre_b, x, Dm, Dm);           // 7
        n = (long long)Lnum * Dm * Dm;                                     // 8
        wconv_kernel<<<(unsigned)((n + 255) / 256), 256>>>(ow, wod, Lnum * Dm, Dm);
        n = (long long)Lnum * FFd * Dm;                                    // 9
        wconv_kernel<<<(unsigned)((n + 255) / 256), 256>>>(fc1_w, w1d, Lnum * FFd, Dm);
        n = (long long)Lnum * Dm * FFd;                                    // 10
        wconv_kernel<<<(unsigned)((n + 255) / 256), 256>>>(fc2_w, w2d, Lnum * Dm, FFd);
    }

    dim3 g768(Dm / BNt, MPAD / BMt);    // (6, 103)
    dim3 gqkv(NQKV / BNt, MPAD / BMt);  // (18, 103)
    dim3 gff(FFd / BNt, MPAD / BMt);    // (24, 103)

    for (int l = 0; l < Lnum; l++) {
        if (l > 0) {
            int tot = Bsz * NPRn * Dm;
            replace_kernel<<<(tot + 255) / 256, 256>>>(x, gprompt, l);
        }
        // attention
        ln_kernel<1><<<MTOK, 256>>>(x, ln1_g + (size_t)l * Dm, ln1_b + (size_t)l * Dm, ae1, Dm, 0);
        bgemm_kernel<0><<<gqkv, 256, GEMM_SMEM>>>(ae1, wqkvd + (size_t)l * NQKV * K768E,
                                                  bqkv + (size_t)l * NQKV,
                                                  nullptr, qkv, K768E, NQKV, MTOK, 0);
        attn_kernel<<<Bsz * Hn, 256, attn_smem>>>(qkv, ae1);
        bgemm_kernel<2><<<g768, 256, GEMM_SMEM>>>(ae1, wod + (size_t)l * Dm * K768E,
                                                  ob + (size_t)l * Dm,
                                                  x, x, K768E, Dm, MTOK, Dm);
        // MLP
        ln_kernel<1><<<MTOK, 256>>>(x, ln2_g + (size_t)l * Dm, ln2_b + (size_t)l * Dm, ae1, Dm, 0);
        bgemm_kernel<3><<<gff, 256, GEMM_SMEM>>>(ae1, w1d + (size_t)l * FFd * K768E,
                                                 fc1_b + (size_t)l * FFd,
                                                 nullptr, ae2, K768E, FFd, MTOK, 0);
        bgemm_kernel<2><<<g768, 256, GEMM_SMEM>>>(ae2, w2d + (size_t)l * Dm * KFFE,
                                                  fc2_b + (size_t)l * Dm,
                                                  x, x, KFFE, Dm, MTOK, Dm);
    }

    ln_kernel<0><<<Bsz, 256>>>(x, post_g, post_b, out, STOK * Dm, Dm);
}